// round 5
// baseline (speedup 1.0000x reference)
#include <cuda_runtime.h>
#include <cuda_fp16.h>
#include <math.h>
#include <stdint.h>

#define NIMG  256
#define PLANE 65536
#define TOT   16777216

// Scratch (__device__ globals per allocation rules)
__device__ float    g_A[TOT];
__device__ float    g_B[TOT];
__device__ uint32_t g_O1p[TOT/2];      // layer1 output, channel-pair half2 packed
__device__ float    g_hdump[4*PLANE];
__device__ uint32_t g_Wpk1[9*2560];    // packed fp16x2 weights [stage][128oc][pitch20]
__device__ uint32_t g_Wpk2[18*2560];

__device__ __forceinline__ float sigm(float x) { return 1.f/(1.f+__expf(-x)); }

// Pre-pack weights: [stage m (k32)][oc 0..127][kpair 0..15, pad to 20]
// k_global = tap*IC + ic ; pitch 20 makes A-frag LDS conflict-free (20g+tig mod 32 distinct)
__global__ void pack_w(const float* __restrict__ w, uint32_t* __restrict__ dst, int IC) {
    int idx = blockIdx.x * 256 + threadIdx.x;
    int total = (IC * 9 / 32) * 2560;
    if (idx >= total) return;
    int m = idx / 2560, rem = idx - m * 2560, oc = rem / 20, kp = rem - oc * 20;
    uint32_t v = 0;
    if (kp < 16) {
        int kg = m * 32 + 2 * kp;
        int tap = kg / IC, ic = kg - tap * IC;
        __half2 h = __floats2half2_rn(w[(oc * IC + ic) * 9 + tap],
                                      w[(oc * IC + ic + 1) * 9 + tap]);
        v = *(uint32_t*)&h;
    }
    dst[idx] = v;
}

// Conv3x3 (pad1) implicit GEMM, mma.sync m16n8k16 fp16 (f32 acc), fused minGRU epilogue.
// 256 threads (8 warps), 2 CTAs/SM. CTA tile: 128oc x 128px (4 rows). Grid 2048.
// Weights streamed per-k32-stage with double buffering (prefetch overlaps mma).
// PIN: input is packed half2 channel-pairs (layer 2) vs fp32 planes (layer 1).
template<int IC, bool PIN>
__global__ void __launch_bounds__(256, 2)
conv_mma(const void* __restrict__ xin_, const uint32_t* __restrict__ wpk,
         const float* __restrict__ bias,
         float* __restrict__ Aout, float* __restrict__ Bout)
{
    extern __shared__ uint32_t sm[];
    constexpr int NST = IC * 9 / 32;
    uint32_t* ws    = sm;                 // 2 x 2560 double-buffered weight stage
    uint32_t* tile2 = sm + 5120;          // [IC/2][6 rows][36] half2

    const int tid = threadIdx.x;
    const int wv = tid >> 5, lane = tid & 31;
    const int g = lane >> 2, tig = lane & 3;
    const int mw = wv & 3, nw = wv >> 2;
    const int n0 = nw * 64;
    const int blk = blockIdx.x, band = blk & 7, n = blk >> 3, r0 = band * 4;
    const int ro = mw * 16 + g;

    // Padded input tile: rows r0-1..r0+4 (6), cols -1..33 (36), channel-pair half2
    for (int idx = tid; idx < (IC / 2) * 216; idx += 256) {
        int icp = idx / 216, rem = idx - icp * 216, r = rem / 36, c = rem - r * 36;
        int gr = r0 + r - 1, gc = c - 1;
        uint32_t v = 0;
        if ((unsigned)gr < 32u && (unsigned)gc < 32u) {
            if (PIN) {
                v = ((const uint32_t*)xin_)[n * 32768 + icp * 1024 + (gr << 5) + gc];
            } else {
                const float* x = (const float*)xin_;
                int base = ((n * IC + 2 * icp) << 10) + (gr << 5) + gc;
                __half2 h = __floats2half2_rn(x[base], x[base + 1024]);
                v = *(uint32_t*)&h;
            }
        }
        tile2[idx] = v;
    }
    // Prefetch weight stage 0
    {
        const float4* src = (const float4*)wpk;
        float4* d4 = (float4*)ws;
        for (int i = tid; i < 640; i += 256) d4[i] = src[i];
    }
    __syncthreads();

    float acc[2][8][4];
    #pragma unroll
    for (int f = 0; f < 2; f++)
        #pragma unroll
        for (int nt = 0; nt < 8; nt++)
            #pragma unroll
            for (int j = 0; j < 4; j++) acc[f][nt][j] = 0.f;

    for (int m = 0; m < NST; m++) {
        if (m + 1 < NST) {   // prefetch next stage into the other buffer
            const float4* src = (const float4*)(wpk + (m + 1) * 2560);
            float4* d4 = (float4*)(ws + ((m + 1) & 1) * 2560);
            for (int i = tid; i < 640; i += 256) d4[i] = src[i];
        }
        const uint32_t* wrow = ws + (m & 1) * 2560;
        #pragma unroll
        for (int sub = 0; sub < 2; sub++) {
            const int kg0 = m * 32 + sub * 16;
            const int tap = kg0 / IC;
            const int icp0 = (kg0 - tap * IC) >> 1;
            const int dr = tap / 3, dc = tap - dr * 3;
            const int soff = dr * 36 + dc;
            const int ks = sub * 8 + tig;

            uint32_t a[2][4];
            a[0][0] = wrow[ro * 20 + ks];            a[0][1] = wrow[(ro + 8) * 20 + ks];
            a[0][2] = wrow[ro * 20 + ks + 4];        a[0][3] = wrow[(ro + 8) * 20 + ks + 4];
            a[1][0] = wrow[(ro + 64) * 20 + ks];     a[1][1] = wrow[(ro + 72) * 20 + ks];
            a[1][2] = wrow[(ro + 64) * 20 + ks + 4]; a[1][3] = wrow[(ro + 72) * 20 + ks + 4];

            const uint32_t* tb = tile2 + (icp0 + tig) * 216 + soff;
            uint32_t b0[8], b1[8];
            #pragma unroll
            for (int nt = 0; nt < 8; nt++) {
                int px = n0 + nt * 8 + g;
                int sp = (px >> 5) * 36 + (px & 31);
                b0[nt] = tb[sp];
                b1[nt] = tb[sp + 4 * 216];
            }
            #pragma unroll
            for (int f = 0; f < 2; f++)
                #pragma unroll
                for (int nt = 0; nt < 8; nt++)
                    asm volatile(
                        "mma.sync.aligned.m16n8k16.row.col.f32.f16.f16.f32 "
                        "{%0,%1,%2,%3}, {%4,%5,%6,%7}, {%8,%9}, {%0,%1,%2,%3};"
                        : "+f"(acc[f][nt][0]), "+f"(acc[f][nt][1]),
                          "+f"(acc[f][nt][2]), "+f"(acc[f][nt][3])
                        : "r"(a[f][0]), "r"(a[f][1]), "r"(a[f][2]), "r"(a[f][3]),
                          "r"(b0[nt]), "r"(b1[nt]));
        }
        __syncthreads();
    }

    // Fused minGRU epilogue: a = 1 - sigmoid(gate), b = sigmoid(gate) * g(hidden)
    const float bg0 = __ldg(bias + ro),      bg1 = __ldg(bias + ro + 8);
    const float bh0 = __ldg(bias + 64 + ro), bh1 = __ldg(bias + 64 + ro + 8);
    const int sp0 = band * 128 + n0 + 2 * tig;
    #pragma unroll
    for (int nt = 0; nt < 8; nt++) {
        #pragma unroll
        for (int h = 0; h < 2; h++) {
            const int oc = ro + 8 * h;
            const float bg = h ? bg1 : bg0, bh = h ? bh1 : bh0;
            float gv0 = acc[0][nt][2*h]     + bg;
            float gv1 = acc[0][nt][2*h + 1] + bg;
            float hv0 = acc[1][nt][2*h]     + bh;
            float hv1 = acc[1][nt][2*h + 1] + bh;
            float z0 = sigm(gv0), z1 = sigm(gv1);
            float q0 = (hv0 >= 0.f) ? hv0 + 0.5f : sigm(hv0);
            float q1 = (hv1 >= 0.f) ? hv1 + 0.5f : sigm(hv1);
            int off = ((n * 64 + oc) << 10) + sp0 + nt * 8;
            *(float2*)(Aout + off) = make_float2(1.f - z0, 1.f - z1);
            *(float2*)(Bout + off) = make_float2(z0 * q0, z1 * q1);
        }
    }
}

// Scan layer 1: h_t = a_t h_{t-1} + b_t, h=-0.5 start; one thread per channel PAIR.
// Writes packed half2 O1 (exactly the rounding conv2 applies anyway) + fp32 h1.
__global__ void __launch_bounds__(256)
scan1_k(const float* __restrict__ A, const float* __restrict__ Bv,
        uint32_t* __restrict__ o1p, float* __restrict__ h1)
{
    int idx = blockIdx.x * 256 + threadIdx.x;       // 131072
    int b = idx >> 15, rem = idx & 32767;
    int icp = rem >> 10, px = rem & 1023;
    size_t base = (size_t)b * 64 * 65536 + icp * 2048 + px;
    float h0 = 0.5f, h1v = 0.5f;
    #pragma unroll 4
    for (int t = 0; t < 64; t++) {
        size_t off = base + (size_t)t * 65536;
        float a0 = A[off],        c0 = Bv[off];
        float a1 = A[off + 1024], c1 = Bv[off + 1024];
        h0  = fmaf(a0, h0,  c0);
        h1v = fmaf(a1, h1v, c1);
        __half2 hh = __floats2half2_rn(h0, h1v);
        o1p[(size_t)(b * 64 + t) * 32768 + rem] = *(uint32_t*)&hh;
    }
    h1[b * 65536 + icp * 2048 + px]        = h0;
    h1[b * 65536 + icp * 2048 + 1024 + px] = h1v;
}

// Scan layer 2: fp32 out (final), float2 vectorized.
__global__ void __launch_bounds__(256)
scan2_k(const float* __restrict__ A, const float* __restrict__ Bv,
        float* __restrict__ out, float* __restrict__ h2)
{
    int idx = blockIdx.x * 256 + threadIdx.x;       // 131072 float2 lanes
    int b = idx >> 15, j = idx & 32767;
    size_t base = (size_t)b * 64 * 32768 + j;
    const float2* A2 = (const float2*)A;
    const float2* B2 = (const float2*)Bv;
    float2* o2 = (float2*)out;
    float h0 = 0.5f, h1v = 0.5f;
    #pragma unroll 4
    for (int t = 0; t < 64; t++) {
        size_t off = base + (size_t)t * 32768;
        float2 a = A2[off], c = B2[off];
        h0  = fmaf(a.x, h0,  c.x);
        h1v = fmaf(a.y, h1v, c.y);
        o2[off] = make_float2(h0, h1v);
    }
    ((float2*)h2)[b * 32768 + j] = make_float2(h0, h1v);
}

extern "C" void kernel_launch(void* const* d_in, const int* in_sizes, int n_in,
                              void* d_out, int out_size) {
    const float* x  = (const float*)d_in[0];
    const float* w1 = (const float*)d_in[1];
    const float* b1 = (const float*)d_in[2];
    const float* w2 = (const float*)d_in[3];
    const float* b2 = (const float*)d_in[4];
    float* out = (float*)d_out;

    float *pA, *pB, *pH;
    uint32_t *pO1p, *pW1, *pW2;
    cudaGetSymbolAddress((void**)&pA,   g_A);
    cudaGetSymbolAddress((void**)&pB,   g_B);
    cudaGetSymbolAddress((void**)&pO1p, g_O1p);
    cudaGetSymbolAddress((void**)&pH,   g_hdump);
    cudaGetSymbolAddress((void**)&pW1,  g_Wpk1);
    cudaGetSymbolAddress((void**)&pW2,  g_Wpk2);

    const int SMEM1 = (5120 + 16 * 216) * 4;   // 34304
    const int SMEM2 = (5120 + 32 * 216) * 4;   // 48128
    cudaFuncSetAttribute(conv_mma<32,false>, cudaFuncAttributeMaxDynamicSharedMemorySize, SMEM1);
    cudaFuncSetAttribute(conv_mma<64,true>,  cudaFuncAttributeMaxDynamicSharedMemorySize, SMEM2);

    bool full = (out_size >= TOT + 8 * PLANE);
    float* h1 = full ? (out + TOT)             : pH;
    float* h2 = full ? (out + TOT + 4 * PLANE) : pH;

    pack_w<<<90, 256>>>(w1, pW1, 32);
    pack_w<<<180, 256>>>(w2, pW2, 64);
    conv_mma<32,false><<<2048, 256, SMEM1>>>(x, pW1, b1, pA, pB);
    scan1_k<<<512, 256>>>(pA, pB, pO1p, h1);
    conv_mma<64,true><<<2048, 256, SMEM2>>>(pO1p, pW2, b2, pA, pB);
    scan2_k<<<512, 256>>>(pA, pB, out, h2);
}

// round 6
// speedup vs baseline: 1.1552x; 1.1552x over previous
#include <cuda_runtime.h>
#include <cuda_fp16.h>
#include <math.h>
#include <stdint.h>

#define NIMG  256
#define PLANE 65536
#define TOT   16777216

// Scratch (__device__ globals per allocation rules)
__device__ float    g_A[TOT];
__device__ float    g_B[TOT];
__device__ uint32_t g_O1p[TOT/2];      // layer1 output, channel-pair half2 packed
__device__ float    g_hdump[4*PLANE];
__device__ uint32_t g_Wpk1[9*2304];    // packed fp16x2 weights [stage][128oc][pitch18]
__device__ uint32_t g_Wpk2[18*2304];

__device__ __forceinline__ float sigm(float x) { return 1.f/(1.f+__expf(-x)); }

// Pre-pack weights to half2 pairs: [stage m(k32)][oc 0..127][kpair 0..15 (+2 pad)]
__global__ void pack_w(const float* __restrict__ w, uint32_t* __restrict__ dst, int IC) {
    int idx = blockIdx.x * 256 + threadIdx.x;
    int total = (IC * 9 / 32) * 2304;
    if (idx >= total) return;
    int m = idx / 2304, rem = idx - m * 2304, oc = rem / 18, kp = rem - oc * 18;
    uint32_t v = 0;
    if (kp < 16) {
        int kg = m * 32 + 2 * kp;
        int tap = kg / IC, ic = kg - tap * IC;
        __half2 h = __floats2half2_rn(w[(oc * IC + ic) * 9 + tap],
                                      w[(oc * IC + ic + 1) * 9 + tap]);
        v = *(uint32_t*)&h;
    }
    dst[idx] = v;
}

// Conv3x3 (pad1) implicit GEMM via mma.sync m16n8k16 fp16 (f32 acc) + fused minGRU
// epilogue. Grid 1024 = 256 images x 4 bands(8 rows). 512 threads = 16 warps,
// warp tile 32oc x 64px; ALL weights smem-resident; zero in-mainloop syncs.
// PIN: input is packed half2 channel-pairs (layer 2) vs fp32 planes (layer 1).
template<int IC, bool PIN>
__global__ void __launch_bounds__(512, 1)
conv_mma(const void* __restrict__ xin_, const uint32_t* __restrict__ wpk,
         const float* __restrict__ bias,
         float* __restrict__ Aout, float* __restrict__ Bout)
{
    extern __shared__ uint32_t sm[];
    constexpr int NST = IC * 9 / 32;           // k32 stages (9 / 18)
    uint32_t* ws    = sm;                      // NST*2304 u32
    uint32_t* tile2 = sm + NST * 2304;         // [IC/2][10 rows][36 cols] half2

    const int tid = threadIdx.x;
    const int wv = tid >> 5, lane = tid & 31;
    const int g = lane >> 2, tig = lane & 3;
    const int mw = wv & 3, nw = wv >> 2;
    const int n0 = nw * 64;
    const int blk = blockIdx.x, band = blk & 3, n = blk >> 2, r0 = band * 8;
    const int ro = mw * 16 + g;

    // All weight stages -> smem (L2-hot float4 copy)
    {
        const float4* src = (const float4*)wpk;
        float4* d4 = (float4*)ws;
        for (int i = tid; i < NST * 576; i += 512) d4[i] = src[i];
    }
    // Padded input tile: rows r0-1..r0+8 (10), cols -1..33 (36), channel-pair half2
    for (int idx = tid; idx < (IC / 2) * 360; idx += 512) {
        int icp = idx / 360, rem = idx - icp * 360, r = rem / 36, c = rem - r * 36;
        int gr = r0 + r - 1, gc = c - 1;
        uint32_t v = 0;
        if ((unsigned)gr < 32u && (unsigned)gc < 32u) {
            if (PIN) {
                v = ((const uint32_t*)xin_)[n * 32768 + icp * 1024 + (gr << 5) + gc];
            } else {
                const float* x = (const float*)xin_;
                int base = ((n * IC + 2 * icp) << 10) + (gr << 5) + gc;
                __half2 h = __floats2half2_rn(x[base], x[base + 1024]);
                v = *(uint32_t*)&h;
            }
        }
        tile2[idx] = v;
    }
    __syncthreads();

    float acc[2][8][4];
    #pragma unroll
    for (int f = 0; f < 2; f++)
        #pragma unroll
        for (int nt = 0; nt < 8; nt++)
            #pragma unroll
            for (int j = 0; j < 4; j++) acc[f][nt][j] = 0.f;

    for (int m = 0; m < NST; m++) {
        const uint32_t* wrow = ws + m * 2304;
        #pragma unroll
        for (int sub = 0; sub < 2; sub++) {
            const int kg0 = m * 32 + sub * 16;
            const int tap = kg0 / IC;
            const int icp0 = (kg0 - tap * IC) >> 1;
            const int dr = tap / 3, dc = tap - dr * 3;
            const int soff = dr * 36 + dc;
            const int ks = sub * 8 + tig;

            uint32_t a[2][4];
            a[0][0] = wrow[ro * 18 + ks];            a[0][1] = wrow[(ro + 8) * 18 + ks];
            a[0][2] = wrow[ro * 18 + ks + 4];        a[0][3] = wrow[(ro + 8) * 18 + ks + 4];
            a[1][0] = wrow[(ro + 64) * 18 + ks];     a[1][1] = wrow[(ro + 72) * 18 + ks];
            a[1][2] = wrow[(ro + 64) * 18 + ks + 4]; a[1][3] = wrow[(ro + 72) * 18 + ks + 4];

            const uint32_t* tb = tile2 + (icp0 + tig) * 360 + soff;
            uint32_t b0[8], b1[8];
            #pragma unroll
            for (int nt = 0; nt < 8; nt++) {
                int px = n0 + nt * 8 + g;
                int sp = (px >> 5) * 36 + (px & 31);
                b0[nt] = tb[sp];
                b1[nt] = tb[sp + 4 * 360];
            }
            #pragma unroll
            for (int f = 0; f < 2; f++)
                #pragma unroll
                for (int nt = 0; nt < 8; nt++)
                    asm volatile(
                        "mma.sync.aligned.m16n8k16.row.col.f32.f16.f16.f32 "
                        "{%0,%1,%2,%3}, {%4,%5,%6,%7}, {%8,%9}, {%0,%1,%2,%3};"
                        : "+f"(acc[f][nt][0]), "+f"(acc[f][nt][1]),
                          "+f"(acc[f][nt][2]), "+f"(acc[f][nt][3])
                        : "r"(a[f][0]), "r"(a[f][1]), "r"(a[f][2]), "r"(a[f][3]),
                          "r"(b0[nt]), "r"(b1[nt]));
        }
    }

    // Fused minGRU epilogue: a = 1 - sigmoid(gate), b = sigmoid(gate) * g(hidden)
    const float bg0 = __ldg(bias + ro),      bg1 = __ldg(bias + ro + 8);
    const float bh0 = __ldg(bias + 64 + ro), bh1 = __ldg(bias + 64 + ro + 8);
    const int sp0 = band * 256 + n0 + 2 * tig;
    #pragma unroll
    for (int nt = 0; nt < 8; nt++) {
        #pragma unroll
        for (int h = 0; h < 2; h++) {
            const int oc = ro + 8 * h;
            const float bg = h ? bg1 : bg0, bh = h ? bh1 : bh0;
            float gv0 = acc[0][nt][2*h]     + bg;
            float gv1 = acc[0][nt][2*h + 1] + bg;
            float hv0 = acc[1][nt][2*h]     + bh;
            float hv1 = acc[1][nt][2*h + 1] + bh;
            float z0 = sigm(gv0), z1 = sigm(gv1);
            float q0 = (hv0 >= 0.f) ? hv0 + 0.5f : sigm(hv0);
            float q1 = (hv1 >= 0.f) ? hv1 + 0.5f : sigm(hv1);
            int off = ((n * 64 + oc) << 10) + sp0 + nt * 8;
            *(float2*)(Aout + off) = make_float2(1.f - z0, 1.f - z1);
            *(float2*)(Bout + off) = make_float2(z0 * q0, z1 * q1);
        }
    }
}

// Scan layer 1: one thread per channel PAIR; writes packed half2 O1 (exactly the
// rounding conv2 applies anyway) + fp32 h1.
__global__ void __launch_bounds__(256)
scan1_k(const float* __restrict__ A, const float* __restrict__ Bv,
        uint32_t* __restrict__ o1p, float* __restrict__ h1)
{
    int idx = blockIdx.x * 256 + threadIdx.x;       // 131072
    int b = idx >> 15, rem = idx & 32767;
    int icp = rem >> 10, px = rem & 1023;
    size_t base = (size_t)b * 64 * 65536 + icp * 2048 + px;
    float h0 = 0.5f, h1v = 0.5f;
    #pragma unroll 4
    for (int t = 0; t < 64; t++) {
        size_t off = base + (size_t)t * 65536;
        float a0 = A[off],        c0 = Bv[off];
        float a1 = A[off + 1024], c1 = Bv[off + 1024];
        h0  = fmaf(a0, h0,  c0);
        h1v = fmaf(a1, h1v, c1);
        __half2 hh = __floats2half2_rn(h0, h1v);
        o1p[(size_t)(b * 64 + t) * 32768 + rem] = *(uint32_t*)&hh;
    }
    h1[b * 65536 + icp * 2048 + px]        = h0;
    h1[b * 65536 + icp * 2048 + 1024 + px] = h1v;
}

// Scan layer 2: fp32 out (final), float2 vectorized.
__global__ void __launch_bounds__(256)
scan2_k(const float* __restrict__ A, const float* __restrict__ Bv,
        float* __restrict__ out, float* __restrict__ h2)
{
    int idx = blockIdx.x * 256 + threadIdx.x;       // 131072 float2 lanes
    int b = idx >> 15, j = idx & 32767;
    size_t base = (size_t)b * 64 * 32768 + j;
    const float2* A2 = (const float2*)A;
    const float2* B2 = (const float2*)Bv;
    float2* o2 = (float2*)out;
    float h0 = 0.5f, h1v = 0.5f;
    #pragma unroll 4
    for (int t = 0; t < 64; t++) {
        size_t off = base + (size_t)t * 32768;
        float2 a = A2[off], c = B2[off];
        h0  = fmaf(a.x, h0,  c.x);
        h1v = fmaf(a.y, h1v, c.y);
        o2[off] = make_float2(h0, h1v);
    }
    ((float2*)h2)[b * 32768 + j] = make_float2(h0, h1v);
}

extern "C" void kernel_launch(void* const* d_in, const int* in_sizes, int n_in,
                              void* d_out, int out_size) {
    const float* x  = (const float*)d_in[0];
    const float* w1 = (const float*)d_in[1];
    const float* b1 = (const float*)d_in[2];
    const float* w2 = (const float*)d_in[3];
    const float* b2 = (const float*)d_in[4];
    float* out = (float*)d_out;

    float *pA, *pB, *pH;
    uint32_t *pO1p, *pW1, *pW2;
    cudaGetSymbolAddress((void**)&pA,   g_A);
    cudaGetSymbolAddress((void**)&pB,   g_B);
    cudaGetSymbolAddress((void**)&pO1p, g_O1p);
    cudaGetSymbolAddress((void**)&pH,   g_hdump);
    cudaGetSymbolAddress((void**)&pW1,  g_Wpk1);
    cudaGetSymbolAddress((void**)&pW2,  g_Wpk2);

    const int SMEM1 = (9 * 2304 + 16 * 360) * 4;    // 105984
    const int SMEM2 = (18 * 2304 + 32 * 360) * 4;   // 211968
    cudaFuncSetAttribute(conv_mma<32,false>, cudaFuncAttributeMaxDynamicSharedMemorySize, SMEM1);
    cudaFuncSetAttribute(conv_mma<64,true>,  cudaFuncAttributeMaxDynamicSharedMemorySize, SMEM2);

    bool full = (out_size >= TOT + 8 * PLANE);
    float* h1 = full ? (out + TOT)             : pH;
    float* h2 = full ? (out + TOT + 4 * PLANE) : pH;

    pack_w<<<81, 256>>>(w1, pW1, 32);
    pack_w<<<162, 256>>>(w2, pW2, 64);
    conv_mma<32,false><<<1024, 512, SMEM1>>>(x, pW1, b1, pA, pB);
    scan1_k<<<512, 256>>>(pA, pB, pO1p, h1);
    conv_mma<64,true><<<1024, 512, SMEM2>>>(pO1p, pW2, b2, pA, pB);
    scan2_k<<<512, 256>>>(pA, pB, out, h2);
}

// round 7
// speedup vs baseline: 1.2542x; 1.0857x over previous
#include <cuda_runtime.h>
#include <cuda_fp16.h>
#include <math.h>
#include <stdint.h>

#define NIMG  256
#define PLANE 65536
#define TOT   16777216

// Scratch (__device__ globals per allocation rules)
__device__ uint32_t g_AB[TOT];         // packed half2 (a, b) per element
__device__ uint32_t g_O1p[TOT/2];      // layer1 output, channel-pair half2 packed
__device__ float    g_hdump[4*PLANE];
__device__ uint32_t g_Wpk1[9*2304];    // packed fp16x2 weights [stage][128oc][pitch18]
__device__ uint32_t g_Wpk2[18*2304];

__device__ __forceinline__ float sigm(float x) { return 1.f/(1.f+__expf(-x)); }
__device__ __forceinline__ uint32_t pkh2(float a, float b) {
    __half2 h = __floats2half2_rn(a, b);
    return *(uint32_t*)&h;
}

// Pre-pack weights to half2 pairs: [stage m(k32)][oc 0..127][kpair 0..15 (+2 pad)]
__global__ void pack_w(const float* __restrict__ w, uint32_t* __restrict__ dst, int IC) {
    int idx = blockIdx.x * 256 + threadIdx.x;
    int total = (IC * 9 / 32) * 2304;
    if (idx >= total) return;
    int m = idx / 2304, rem = idx - m * 2304, oc = rem / 18, kp = rem - oc * 18;
    uint32_t v = 0;
    if (kp < 16) {
        int kg = m * 32 + 2 * kp;
        int tap = kg / IC, ic = kg - tap * IC;
        __half2 h = __floats2half2_rn(w[(oc * IC + ic) * 9 + tap],
                                      w[(oc * IC + ic + 1) * 9 + tap]);
        v = *(uint32_t*)&h;
    }
    dst[idx] = v;
}

// Conv3x3 (pad1) implicit GEMM via mma.sync m16n8k16 fp16 (f32 acc) + fused minGRU
// epilogue writing packed half2 (a=1-z, b=z*g(h)) coefficients.
// Grid 1024 = 256 images x 4 bands(8 rows). 512 threads = 16 warps,
// warp tile 32oc x 64px; ALL weights smem-resident; zero in-mainloop syncs.
template<int IC, bool PIN>
__global__ void __launch_bounds__(512, 1)
conv_mma(const void* __restrict__ xin_, const uint32_t* __restrict__ wpk,
         const float* __restrict__ bias,
         uint32_t* __restrict__ ABout)
{
    extern __shared__ uint32_t sm[];
    constexpr int NST = IC * 9 / 32;           // k32 stages (9 / 18)
    uint32_t* ws    = sm;                      // NST*2304 u32
    uint32_t* tile2 = sm + NST * 2304;         // [IC/2][10 rows][36 cols] half2

    const int tid = threadIdx.x;
    const int wv = tid >> 5, lane = tid & 31;
    const int g = lane >> 2, tig = lane & 3;
    const int mw = wv & 3, nw = wv >> 2;
    const int n0 = nw * 64;
    const int blk = blockIdx.x, band = blk & 3, n = blk >> 2, r0 = band * 8;
    const int ro = mw * 16 + g;

    // All weight stages -> smem (L2-hot float4 copy)
    {
        const float4* src = (const float4*)wpk;
        float4* d4 = (float4*)ws;
        for (int i = tid; i < NST * 576; i += 512) d4[i] = src[i];
    }
    // Padded input tile: rows r0-1..r0+8 (10), cols -1..33 (36), channel-pair half2
    for (int idx = tid; idx < (IC / 2) * 360; idx += 512) {
        int icp = idx / 360, rem = idx - icp * 360, r = rem / 36, c = rem - r * 36;
        int gr = r0 + r - 1, gc = c - 1;
        uint32_t v = 0;
        if ((unsigned)gr < 32u && (unsigned)gc < 32u) {
            if (PIN) {
                v = ((const uint32_t*)xin_)[n * 32768 + icp * 1024 + (gr << 5) + gc];
            } else {
                const float* x = (const float*)xin_;
                int base = ((n * IC + 2 * icp) << 10) + (gr << 5) + gc;
                __half2 h = __floats2half2_rn(x[base], x[base + 1024]);
                v = *(uint32_t*)&h;
            }
        }
        tile2[idx] = v;
    }
    __syncthreads();

    float acc[2][8][4];
    #pragma unroll
    for (int f = 0; f < 2; f++)
        #pragma unroll
        for (int nt = 0; nt < 8; nt++)
            #pragma unroll
            for (int j = 0; j < 4; j++) acc[f][nt][j] = 0.f;

    for (int m = 0; m < NST; m++) {
        const uint32_t* wrow = ws + m * 2304;
        #pragma unroll
        for (int sub = 0; sub < 2; sub++) {
            const int kg0 = m * 32 + sub * 16;
            const int tap = kg0 / IC;
            const int icp0 = (kg0 - tap * IC) >> 1;
            const int dr = tap / 3, dc = tap - dr * 3;
            const int soff = dr * 36 + dc;
            const int ks = sub * 8 + tig;

            uint32_t a[2][4];
            a[0][0] = wrow[ro * 18 + ks];            a[0][1] = wrow[(ro + 8) * 18 + ks];
            a[0][2] = wrow[ro * 18 + ks + 4];        a[0][3] = wrow[(ro + 8) * 18 + ks + 4];
            a[1][0] = wrow[(ro + 64) * 18 + ks];     a[1][1] = wrow[(ro + 72) * 18 + ks];
            a[1][2] = wrow[(ro + 64) * 18 + ks + 4]; a[1][3] = wrow[(ro + 72) * 18 + ks + 4];

            const uint32_t* tb = tile2 + (icp0 + tig) * 360 + soff;
            uint32_t b0[8], b1[8];
            #pragma unroll
            for (int nt = 0; nt < 8; nt++) {
                int px = n0 + nt * 8 + g;
                int sp = (px >> 5) * 36 + (px & 31);
                b0[nt] = tb[sp];
                b1[nt] = tb[sp + 4 * 360];
            }
            #pragma unroll
            for (int f = 0; f < 2; f++)
                #pragma unroll
                for (int nt = 0; nt < 8; nt++)
                    asm volatile(
                        "mma.sync.aligned.m16n8k16.row.col.f32.f16.f16.f32 "
                        "{%0,%1,%2,%3}, {%4,%5,%6,%7}, {%8,%9}, {%0,%1,%2,%3};"
                        : "+f"(acc[f][nt][0]), "+f"(acc[f][nt][1]),
                          "+f"(acc[f][nt][2]), "+f"(acc[f][nt][3])
                        : "r"(a[f][0]), "r"(a[f][1]), "r"(a[f][2]), "r"(a[f][3]),
                          "r"(b0[nt]), "r"(b1[nt]));
        }
    }

    // Fused minGRU epilogue -> packed half2 (a, b) per element, uint2 per px pair
    const float bg0 = __ldg(bias + ro),      bg1 = __ldg(bias + ro + 8);
    const float bh0 = __ldg(bias + 64 + ro), bh1 = __ldg(bias + 64 + ro + 8);
    const int sp0 = band * 256 + n0 + 2 * tig;
    #pragma unroll
    for (int nt = 0; nt < 8; nt++) {
        #pragma unroll
        for (int h = 0; h < 2; h++) {
            const int oc = ro + 8 * h;
            const float bg = h ? bg1 : bg0, bh = h ? bh1 : bh0;
            float gv0 = acc[0][nt][2*h]     + bg;
            float gv1 = acc[0][nt][2*h + 1] + bg;
            float hv0 = acc[1][nt][2*h]     + bh;
            float hv1 = acc[1][nt][2*h + 1] + bh;
            float z0 = sigm(gv0), z1 = sigm(gv1);
            float q0 = (hv0 >= 0.f) ? hv0 + 0.5f : sigm(hv0);
            float q1 = (hv1 >= 0.f) ? hv1 + 0.5f : sigm(hv1);
            int off = ((n * 64 + oc) << 10) + sp0 + nt * 8;
            uint2 pk;
            pk.x = pkh2(1.f - z0, z0 * q0);
            pk.y = pkh2(1.f - z1, z1 * q1);
            *(uint2*)(ABout + off) = pk;
        }
    }
}

// Scan layer 1: one thread per channel PAIR; reads packed (a,b) half2;
// writes packed half2 O1 + fp32 h1.
__global__ void __launch_bounds__(256)
scan1_k(const uint32_t* __restrict__ AB,
        uint32_t* __restrict__ o1p, float* __restrict__ h1)
{
    int idx = blockIdx.x * 256 + threadIdx.x;       // 131072
    int b = idx >> 15, rem = idx & 32767;
    int icp = rem >> 10, px = rem & 1023;
    size_t base = (size_t)b * 64 * 65536 + icp * 2048 + px;
    float h0 = 0.5f, h1v = 0.5f;
    #pragma unroll 4
    for (int t = 0; t < 64; t++) {
        size_t off = base + (size_t)t * 65536;
        uint32_t p0 = AB[off], p1 = AB[off + 1024];
        float2 c0 = __half22float2(*(__half2*)&p0);
        float2 c1 = __half22float2(*(__half2*)&p1);
        h0  = fmaf(c0.x, h0,  c0.y);
        h1v = fmaf(c1.x, h1v, c1.y);
        __half2 hh = __floats2half2_rn(h0, h1v);
        o1p[(size_t)(b * 64 + t) * 32768 + rem] = *(uint32_t*)&hh;
    }
    h1[b * 65536 + icp * 2048 + px]        = h0;
    h1[b * 65536 + icp * 2048 + 1024 + px] = h1v;
}

// Scan layer 2: reads packed (a,b); fp32 out (final), float2 stores.
__global__ void __launch_bounds__(256)
scan2_k(const uint32_t* __restrict__ AB,
        float* __restrict__ out, float* __restrict__ h2)
{
    int idx = blockIdx.x * 256 + threadIdx.x;       // 131072 px-pair lanes
    int b = idx >> 15, j = idx & 32767;
    size_t base = (size_t)b * 64 * 32768 + j;
    const uint2* AB2 = (const uint2*)AB;
    float2* o2 = (float2*)out;
    float h0 = 0.5f, h1v = 0.5f;
    #pragma unroll 4
    for (int t = 0; t < 64; t++) {
        size_t off = base + (size_t)t * 32768;
        uint2 p = AB2[off];
        float2 c0 = __half22float2(*(__half2*)&p.x);
        float2 c1 = __half22float2(*(__half2*)&p.y);
        h0  = fmaf(c0.x, h0,  c0.y);
        h1v = fmaf(c1.x, h1v, c1.y);
        o2[off] = make_float2(h0, h1v);
    }
    ((float2*)h2)[b * 32768 + j] = make_float2(h0, h1v);
}

extern "C" void kernel_launch(void* const* d_in, const int* in_sizes, int n_in,
                              void* d_out, int out_size) {
    const float* x  = (const float*)d_in[0];
    const float* w1 = (const float*)d_in[1];
    const float* b1 = (const float*)d_in[2];
    const float* w2 = (const float*)d_in[3];
    const float* b2 = (const float*)d_in[4];
    float* out = (float*)d_out;

    float *pH;
    uint32_t *pAB, *pO1p, *pW1, *pW2;
    cudaGetSymbolAddress((void**)&pAB,  g_AB);
    cudaGetSymbolAddress((void**)&pO1p, g_O1p);
    cudaGetSymbolAddress((void**)&pH,   g_hdump);
    cudaGetSymbolAddress((void**)&pW1,  g_Wpk1);
    cudaGetSymbolAddress((void**)&pW2,  g_Wpk2);

    const int SMEM1 = (9 * 2304 + 16 * 360) * 4;    // 105984
    const int SMEM2 = (18 * 2304 + 32 * 360) * 4;   // 211968
    cudaFuncSetAttribute(conv_mma<32,false>, cudaFuncAttributeMaxDynamicSharedMemorySize, SMEM1);
    cudaFuncSetAttribute(conv_mma<64,true>,  cudaFuncAttributeMaxDynamicSharedMemorySize, SMEM2);

    bool full = (out_size >= TOT + 8 * PLANE);
    float* h1 = full ? (out + TOT)             : pH;
    float* h2 = full ? (out + TOT + 4 * PLANE) : pH;

    pack_w<<<81, 256>>>(w1, pW1, 32);
    pack_w<<<162, 256>>>(w2, pW2, 64);
    conv_mma<32,false><<<1024, 512, SMEM1>>>(x, pW1, b1, pAB);
    scan1_k<<<512, 256>>>(pAB, pO1p, h1);
    conv_mma<64,true><<<1024, 512, SMEM2>>>(pO1p, pW2, b2, pAB);
    scan2_k<<<512, 256>>>(pAB, out, h2);
}

// round 8
// speedup vs baseline: 1.3728x; 1.0946x over previous
#include <cuda_runtime.h>
#include <cuda_fp16.h>
#include <math.h>
#include <stdint.h>

#define NIMG  256
#define PLANE 65536
#define TOT   16777216

// Scratch (__device__ globals per allocation rules)
__device__ uint32_t g_AB[TOT];         // packed half2 (a, b) per element
__device__ uint32_t g_O1p[TOT/2];      // layer1 output, channel-pair half2 packed
__device__ float    g_hdump[4*PLANE];
__device__ uint32_t g_U1[32768];       // Winograd-transformed weights, fragment order
__device__ uint32_t g_U2[65536];

__device__ __forceinline__ float sigm(float x) { return 1.f/(1.f+__expf(-x)); }
__device__ __forceinline__ uint32_t pkh2(float a, float b) {
    __half2 h = __floats2half2_rn(a, b);
    return *(uint32_t*)&h;
}

// Pack Winograd-transformed weights U = G w G^T (4x4 per oc,ic) into mma-fragment
// order: slab = (p*4 + ocgrp)*2 + f ; per slab KC chunks of 128 u32 (lane*4 + q).
// Lane l, q: row oc = f*64 + ocgrp*16 + l/4 + (q&1)*8 ; k(=ic) = c*16 + 2*(l%4) + (q>>1)*8.
template<int IC>
__global__ void pack_u(const float* __restrict__ w, uint32_t* __restrict__ dst) {
    constexpr int KC = IC / 16;
    int idx = blockIdx.x * 256 + threadIdx.x;
    if (idx >= 128 * KC * 128) return;
    int slab = idx / (KC * 128);
    int rem  = idx - slab * (KC * 128);
    int c = rem >> 7, rem2 = rem & 127;
    int lane = rem2 >> 2, q = rem2 & 3;
    int f  = slab & 1;
    int og = (slab >> 1) & 3;
    int p  = slab >> 3;
    int xi = p >> 2, eta = p & 3;
    int oc = f * 64 + og * 16 + (lane >> 2) + (q & 1) * 8;
    int k  = c * 16 + 2 * (lane & 3) + (q >> 1) * 8;
    const float G[4][3] = {{1,0,0},{0.5f,0.5f,0.5f},{0.5f,-0.5f,0.5f},{0,0,1}};
    float u[2];
    #pragma unroll
    for (int t = 0; t < 2; t++) {
        const float* wp = w + (oc * IC + k + t) * 9;
        float a = 0.f;
        for (int i = 0; i < 3; i++)
            for (int j = 0; j < 3; j++)
                a += G[xi][i] * G[eta][j] * wp[i * 3 + j];
        u[t] = a;
    }
    dst[idx] = pkh2(u[0], u[1]);
}

// Winograd F(2x2,3x3) conv + fused minGRU epilogue.
// Grid 1024 = 256 images x 4 bands (8 rows = 4 tile-rows). 512 threads = 16 warps.
// Warp (og, tg): 32 oc (16 gate og*16.. + paired hidden +64) x tile-row tg (16 tiles).
// Loop 16 transform points: GEMM K=IC from U (gmem, frag-packed) x V (smem),
// fold M into Y via A^T coeffs {0,+-1}. V pitch 72: LDS bank 8*(l%4)+l/4, conflict-free.
template<int IC, bool PIN>
__global__ void __launch_bounds__(512, 1)
conv_wino(const void* __restrict__ xin_, const uint32_t* __restrict__ Upk,
          const float* __restrict__ bias, uint32_t* __restrict__ ABout)
{
    extern __shared__ uint32_t sm[];
    constexpr int KC  = IC / 16;
    constexpr int ICP = IC / 2;
    constexpr int VP  = ICP * 72;          // u32 per transform point
    uint32_t* tile2 = sm;                  // [ICP][10 rows][36 cols] half2
    uint32_t* V     = sm + ICP * 360;      // [16 points][ICP kpairs][72 (64 tiles)]

    const int tid = threadIdx.x;
    const int wv = tid >> 5, lane = tid & 31;
    const int g4 = lane >> 2, tig = lane & 3;
    const int og = wv & 3, tg = wv >> 2;
    const int blk = blockIdx.x, band = blk & 3, n = blk >> 2, r0 = band * 8;

    // Stage padded input: rows r0-1..r0+8 (10), cols -1..33 (36), channel-pair half2
    for (int idx = tid; idx < ICP * 360; idx += 512) {
        int icp = idx / 360, rem = idx - icp * 360, r = rem / 36, c = rem - r * 36;
        int gr = r0 + r - 1, gc = c - 1;
        uint32_t v = 0;
        if ((unsigned)gr < 32u && (unsigned)gc < 32u) {
            if (PIN) {
                v = ((const uint32_t*)xin_)[n * 32768 + icp * 1024 + (gr << 5) + gc];
            } else {
                const float* x = (const float*)xin_;
                int base = ((n * IC + 2 * icp) << 10) + (gr << 5) + gc;
                v = pkh2(x[base], x[base + 1024]);
            }
        }
        tile2[idx] = v;
    }
    __syncthreads();

    // Input transform: per (icpair, tile): V = B^T d B (on half2 = 2 channels at once)
    for (int u = tid; u < ICP * 64; u += 512) {
        int icp = u >> 6, rem = u & 63, tr = rem >> 4, tc = rem & 15;
        const uint32_t* dp = tile2 + icp * 360 + (2 * tr) * 36 + 2 * tc;
        float2 d[4][4];
        #pragma unroll
        for (int i = 0; i < 4; i++)
            #pragma unroll
            for (int j = 0; j < 4; j++) {
                uint32_t raw = dp[i * 36 + j];
                d[i][j] = __half22float2(*(__half2*)&raw);
            }
        float2 t[4][4];
        #pragma unroll
        for (int j = 0; j < 4; j++) {
            t[0][j] = make_float2(d[0][j].x - d[2][j].x, d[0][j].y - d[2][j].y);
            t[1][j] = make_float2(d[1][j].x + d[2][j].x, d[1][j].y + d[2][j].y);
            t[2][j] = make_float2(d[2][j].x - d[1][j].x, d[2][j].y - d[1][j].y);
            t[3][j] = make_float2(d[1][j].x - d[3][j].x, d[1][j].y - d[3][j].y);
        }
        uint32_t* vp = V + icp * 72 + tr * 16 + tc;
        #pragma unroll
        for (int xi = 0; xi < 4; xi++) {
            float2 v0 = make_float2(t[xi][0].x - t[xi][2].x, t[xi][0].y - t[xi][2].y);
            float2 v1 = make_float2(t[xi][1].x + t[xi][2].x, t[xi][1].y + t[xi][2].y);
            float2 v2 = make_float2(t[xi][2].x - t[xi][1].x, t[xi][2].y - t[xi][1].y);
            float2 v3 = make_float2(t[xi][1].x - t[xi][3].x, t[xi][1].y - t[xi][3].y);
            vp[(xi * 4 + 0) * VP] = pkh2(v0.x, v0.y);
            vp[(xi * 4 + 1) * VP] = pkh2(v1.x, v1.y);
            vp[(xi * 4 + 2) * VP] = pkh2(v2.x, v2.y);
            vp[(xi * 4 + 3) * VP] = pkh2(v3.x, v3.y);
        }
    }
    __syncthreads();

    float Y[2][2][4][4];   // [f gate/hid][nf][acc j][di*2+dj]
    #pragma unroll
    for (int f = 0; f < 2; f++)
        #pragma unroll
        for (int nf = 0; nf < 2; nf++)
            #pragma unroll
            for (int j = 0; j < 4; j++)
                #pragma unroll
                for (int e = 0; e < 4; e++) Y[f][nf][j][e] = 0.f;

    for (int p = 0; p < 16; p++) {
        float M[2][2][4];
        #pragma unroll
        for (int f = 0; f < 2; f++)
            #pragma unroll
            for (int nf = 0; nf < 2; nf++)
                #pragma unroll
                for (int j = 0; j < 4; j++) M[f][nf][j] = 0.f;

        const uint32_t* Ub = Upk + (size_t)((p * 4 + og) * 2) * KC * 128;
        const uint32_t* Vb = V + p * VP + tig * 72 + tg * 16 + g4;
        #pragma unroll
        for (int c = 0; c < KC; c++) {
            uint4 a0 = *(const uint4*)(Ub + c * 128 + lane * 4);
            uint4 a1 = *(const uint4*)(Ub + KC * 128 + c * 128 + lane * 4);
            uint32_t b00 = Vb[(c * 8) * 72];
            uint32_t b01 = Vb[(c * 8 + 4) * 72];
            uint32_t b10 = Vb[(c * 8) * 72 + 8];
            uint32_t b11 = Vb[(c * 8 + 4) * 72 + 8];
            #pragma unroll
            for (int f = 0; f < 2; f++) {
                uint4 aa = f ? a1 : a0;
                asm volatile(
                    "mma.sync.aligned.m16n8k16.row.col.f32.f16.f16.f32 "
                    "{%0,%1,%2,%3}, {%4,%5,%6,%7}, {%8,%9}, {%0,%1,%2,%3};"
                    : "+f"(M[f][0][0]), "+f"(M[f][0][1]), "+f"(M[f][0][2]), "+f"(M[f][0][3])
                    : "r"(aa.x), "r"(aa.y), "r"(aa.z), "r"(aa.w), "r"(b00), "r"(b01));
                asm volatile(
                    "mma.sync.aligned.m16n8k16.row.col.f32.f16.f16.f32 "
                    "{%0,%1,%2,%3}, {%4,%5,%6,%7}, {%8,%9}, {%0,%1,%2,%3};"
                    : "+f"(M[f][1][0]), "+f"(M[f][1][1]), "+f"(M[f][1][2]), "+f"(M[f][1][3])
                    : "r"(aa.x), "r"(aa.y), "r"(aa.z), "r"(aa.w), "r"(b10), "r"(b11));
            }
        }
        // Fold M into Y with A^T coeffs: At0 = [1,1,1,0], At1 = [0,1,-1,-1]
        int xi = p >> 2, eta = p & 3;
        float cx0 = (xi == 3) ? 0.f : 1.f;
        float cx1 = (xi == 0) ? 0.f : ((xi == 1) ? 1.f : -1.f);
        float cy0 = (eta == 3) ? 0.f : 1.f;
        float cy1 = (eta == 0) ? 0.f : ((eta == 1) ? 1.f : -1.f);
        float c00 = cx0 * cy0, c01 = cx0 * cy1, c10 = cx1 * cy0, c11 = cx1 * cy1;
        #pragma unroll
        for (int f = 0; f < 2; f++)
            #pragma unroll
            for (int nf = 0; nf < 2; nf++)
                #pragma unroll
                for (int j = 0; j < 4; j++) {
                    float m = M[f][nf][j];
                    Y[f][nf][j][0] = fmaf(c00, m, Y[f][nf][j][0]);
                    Y[f][nf][j][1] = fmaf(c01, m, Y[f][nf][j][1]);
                    Y[f][nf][j][2] = fmaf(c10, m, Y[f][nf][j][2]);
                    Y[f][nf][j][3] = fmaf(c11, m, Y[f][nf][j][3]);
                }
    }

    // Fused minGRU epilogue -> packed half2 (a, b), uint2 per 2x1 px pair
    const float bg0 = __ldg(bias + og * 16 + g4),      bg1 = __ldg(bias + og * 16 + g4 + 8);
    const float bh0 = __ldg(bias + 64 + og * 16 + g4), bh1 = __ldg(bias + 64 + og * 16 + g4 + 8);
    #pragma unroll
    for (int nf = 0; nf < 2; nf++)
        #pragma unroll
        for (int j = 0; j < 4; j++) {
            int oc = og * 16 + g4 + ((j >> 1) * 8);
            int tc = nf * 8 + 2 * tig + (j & 1);
            float bg = (j >> 1) ? bg1 : bg0, bh = (j >> 1) ? bh1 : bh0;
            #pragma unroll
            for (int di = 0; di < 2; di++) {
                int row = r0 + 2 * tg + di;
                float g0 = Y[0][nf][j][di * 2 + 0] + bg;
                float g1 = Y[0][nf][j][di * 2 + 1] + bg;
                float h0 = Y[1][nf][j][di * 2 + 0] + bh;
                float h1 = Y[1][nf][j][di * 2 + 1] + bh;
                float z0 = sigm(g0), z1 = sigm(g1);
                float q0 = (h0 >= 0.f) ? h0 + 0.5f : sigm(h0);
                float q1 = (h1 >= 0.f) ? h1 + 0.5f : sigm(h1);
                uint2 pk;
                pk.x = pkh2(1.f - z0, z0 * q0);
                pk.y = pkh2(1.f - z1, z1 * q1);
                *(uint2*)(ABout + ((n * 64 + oc) << 10) + (row << 5) + 2 * tc) = pk;
            }
        }
}

// Scan layer 1: one thread per channel PAIR; reads packed (a,b) half2;
// writes packed half2 O1 + fp32 h1.
__global__ void __launch_bounds__(256)
scan1_k(const uint32_t* __restrict__ AB,
        uint32_t* __restrict__ o1p, float* __restrict__ h1)
{
    int idx = blockIdx.x * 256 + threadIdx.x;       // 131072
    int b = idx >> 15, rem = idx & 32767;
    int icp = rem >> 10, px = rem & 1023;
    size_t base = (size_t)b * 64 * 65536 + icp * 2048 + px;
    float h0 = 0.5f, h1v = 0.5f;
    #pragma unroll 4
    for (int t = 0; t < 64; t++) {
        size_t off = base + (size_t)t * 65536;
        uint32_t p0 = AB[off], p1 = AB[off + 1024];
        float2 c0 = __half22float2(*(__half2*)&p0);
        float2 c1 = __half22float2(*(__half2*)&p1);
        h0  = fmaf(c0.x, h0,  c0.y);
        h1v = fmaf(c1.x, h1v, c1.y);
        o1p[(size_t)(b * 64 + t) * 32768 + rem] = pkh2(h0, h1v);
    }
    h1[b * 65536 + icp * 2048 + px]        = h0;
    h1[b * 65536 + icp * 2048 + 1024 + px] = h1v;
}

// Scan layer 2: reads packed (a,b); fp32 out (final), float2 stores.
__global__ void __launch_bounds__(256)
scan2_k(const uint32_t* __restrict__ AB,
        float* __restrict__ out, float* __restrict__ h2)
{
    int idx = blockIdx.x * 256 + threadIdx.x;       // 131072 px-pair lanes
    int b = idx >> 15, j = idx & 32767;
    size_t base = (size_t)b * 64 * 32768 + j;
    const uint2* AB2 = (const uint2*)AB;
    float2* o2 = (float2*)out;
    float h0 = 0.5f, h1v = 0.5f;
    #pragma unroll 4
    for (int t = 0; t < 64; t++) {
        size_t off = base + (size_t)t * 32768;
        uint2 p = AB2[off];
        float2 c0 = __half22float2(*(__half2*)&p.x);
        float2 c1 = __half22float2(*(__half2*)&p.y);
        h0  = fmaf(c0.x, h0,  c0.y);
        h1v = fmaf(c1.x, h1v, c1.y);
        o2[off] = make_float2(h0, h1v);
    }
    ((float2*)h2)[b * 32768 + j] = make_float2(h0, h1v);
}

extern "C" void kernel_launch(void* const* d_in, const int* in_sizes, int n_in,
                              void* d_out, int out_size) {
    const float* x  = (const float*)d_in[0];
    const float* w1 = (const float*)d_in[1];
    const float* b1 = (const float*)d_in[2];
    const float* w2 = (const float*)d_in[3];
    const float* b2 = (const float*)d_in[4];
    float* out = (float*)d_out;

    float *pH;
    uint32_t *pAB, *pO1p, *pU1, *pU2;
    cudaGetSymbolAddress((void**)&pAB,  g_AB);
    cudaGetSymbolAddress((void**)&pO1p, g_O1p);
    cudaGetSymbolAddress((void**)&pH,   g_hdump);
    cudaGetSymbolAddress((void**)&pU1,  g_U1);
    cudaGetSymbolAddress((void**)&pU2,  g_U2);

    const int SMEM1 = (16 * 360 + 16 * 16 * 72) * 4;   //  96768
    const int SMEM2 = (32 * 360 + 16 * 32 * 72) * 4;   // 193536
    cudaFuncSetAttribute(conv_wino<32,false>, cudaFuncAttributeMaxDynamicSharedMemorySize, SMEM1);
    cudaFuncSetAttribute(conv_wino<64,true>,  cudaFuncAttributeMaxDynamicSharedMemorySize, SMEM2);

    bool full = (out_size >= TOT + 8 * PLANE);
    float* h1 = full ? (out + TOT)             : pH;
    float* h2 = full ? (out + TOT + 4 * PLANE) : pH;

    pack_u<32><<<128, 256>>>(w1, pU1);
    pack_u<64><<<256, 256>>>(w2, pU2);
    conv_wino<32,false><<<1024, 512, SMEM1>>>(x, pU1, b1, pAB);
    scan1_k<<<512, 256>>>(pAB, pO1p, h1);
    conv_wino<64,true><<<1024, 512, SMEM2>>>(pO1p, pU2, b2, pAB);
    scan2_k<<<512, 256>>>(pAB, out, h2);
}